// round 1
// baseline (speedup 1.0000x reference)
#include <cuda_runtime.h>
#include <cuda_bf16.h>

// adapt_smoothing: out[b,s,f] = sum_{l=0..24} w[l] * x[b, max(s+l-24, 0), f]
// x: [B=32, S=4096, F=512] fp32, w: [K=25] fp32.
//
// Strategy: one thread per (b, f) column marches S_TILE=200 timesteps with a
// 25-deep register ring buffer. S_TILE % 25 == 0 so ring slot == phase index
// (compile-time) -> no register shuffles. Lanes cover consecutive f ->
// fully coalesced 128B loads/stores. 1 LDG + 1 STG + 25 FFMA per output.

#define B_DIM 32
#define S_DIM 4096
#define F_DIM 512
#define K_DIM 25
#define S_TILE 200          // multiple of 25
#define BLOCK_F 128

__global__ __launch_bounds__(BLOCK_F) void adapt_smoothing_kernel(
    const float* __restrict__ x,
    const float* __restrict__ w,
    float* __restrict__ out)
{
    const int f  = blockIdx.x * BLOCK_F + threadIdx.x;   // 0..511
    const int s0 = blockIdx.y * S_TILE;                  // multiple of 25
    const int b  = blockIdx.z;

    const int boff = b * (S_DIM * F_DIM) + f;            // fits in int (64M max)

    // Weights -> registers (broadcast loads, L1-resident after warm lane)
    float rw[K_DIM];
#pragma unroll
    for (int l = 0; l < K_DIM; ++l) rw[l] = __ldg(&w[l]);

    // Ring buffer: invariant buf[t % 25] = x[b, t, f] (with s0 % 25 == 0).
    // Preload the 24 history values x[s0-24 .. s0-1] (clamped to 0) into
    // buf[1..24]; buf[0] is filled at phase 0 of the first inner iteration.
    float buf[K_DIM];
#pragma unroll
    for (int q = 0; q < K_DIM - 1; ++q) {
        int t = s0 - (K_DIM - 1) + q;
        if (t < 0) t = 0;
        buf[q + 1] = x[boff + t * F_DIM];
    }

    for (int j = 0; j < S_TILE; j += K_DIM) {
#pragma unroll
        for (int p = 0; p < K_DIM; ++p) {
            const int t = s0 + j + p;
            const bool in_range = (t < S_DIM);
            float cur = 0.0f;
            if (in_range) cur = x[boff + t * F_DIM];
            buf[p] = cur;   // t % 25 == p

            // out[t] = sum_l rw[l] * x[t-24+l] = sum_l rw[l]*buf[(p+1+l)%25]
            // 4 partial accumulators to break the FFMA dependency chain.
            float a0 = 0.f, a1 = 0.f, a2 = 0.f, a3 = 0.f;
#pragma unroll
            for (int l = 0; l < K_DIM; l += 4) {
                a0 = fmaf(rw[l], buf[(p + 1 + l) % K_DIM], a0);
                if (l + 1 < K_DIM) a1 = fmaf(rw[l + 1], buf[(p + 2 + l) % K_DIM], a1);
                if (l + 2 < K_DIM) a2 = fmaf(rw[l + 2], buf[(p + 3 + l) % K_DIM], a2);
                if (l + 3 < K_DIM) a3 = fmaf(rw[l + 3], buf[(p + 4 + l) % K_DIM], a3);
            }
            const float acc = (a0 + a1) + (a2 + a3);

            if (in_range) out[boff + t * F_DIM] = acc;
        }
    }
}

extern "C" void kernel_launch(void* const* d_in, const int* in_sizes, int n_in,
                              void* d_out, int out_size)
{
    const float* x = (const float*)d_in[0];
    const float* w = (const float*)d_in[1];
    float* out = (float*)d_out;

    const int n_chunks = (S_DIM + S_TILE - 1) / S_TILE;  // 21
    dim3 grid(F_DIM / BLOCK_F, n_chunks, B_DIM);         // (4, 21, 32)
    dim3 block(BLOCK_F);
    adapt_smoothing_kernel<<<grid, block>>>(x, w, out);
}

// round 3
// speedup vs baseline: 2.2271x; 2.2271x over previous
#include <cuda_runtime.h>

// adapt_smoothing: out[b,s,f] = sum_{l=0..24} w[l] * x[b, max(s+l-24,0), f]
// x: [B=32, S=4096, F=512] fp32, w: [K=25] fp32.
//
// v2b (resubmit after infra failure): float2 lanes with packed fma.rn.f32x2
// (sm_103a), 25-deep register ring, weights pre-packed into 64-bit broadcast
// registers, __launch_bounds__(128,4) => 128-reg budget so ring + weights stay
// register-resident and loads can be hoisted for MLP.

#define B_DIM 32
#define S_DIM 4096
#define F_DIM 512
#define K_DIM 25
#define P_DIM (F_DIM / 2)   // 256 float2 columns
#define S_TILE 200          // multiple of 25
#define BLOCK_P 128

typedef unsigned long long u64;

__device__ __forceinline__ u64 pack2(float v) {
    union { float f[2]; u64 u; } c;
    c.f[0] = v; c.f[1] = v;
    return c.u;
}
__device__ __forceinline__ u64 fma2(u64 a, u64 b, u64 c) {
    u64 d; asm("fma.rn.f32x2 %0, %1, %2, %3;" : "=l"(d) : "l"(a), "l"(b), "l"(c)); return d;
}
__device__ __forceinline__ u64 add2(u64 a, u64 b) {
    u64 d; asm("add.rn.f32x2 %0, %1, %2;" : "=l"(d) : "l"(a), "l"(b)); return d;
}

__global__ __launch_bounds__(BLOCK_P, 4) void adapt_smoothing_kernel(
    const float* __restrict__ x,
    const float* __restrict__ w,
    float* __restrict__ out)
{
    const int fp = blockIdx.x * BLOCK_P + threadIdx.x;   // float2 column, 0..255
    const int s0 = blockIdx.y * S_TILE;                  // multiple of 25
    const int b  = blockIdx.z;

    const u64* __restrict__ xv = (const u64*)x;
    u64* __restrict__ ov = (u64*)out;
    const int boff = b * (S_DIM * P_DIM) + fp;           // max 33.5M, fits int

    // Weights -> packed 64-bit broadcast registers (both f32 halves = w[l]).
    u64 pw[K_DIM];
#pragma unroll
    for (int l = 0; l < K_DIM; ++l) pw[l] = pack2(__ldg(&w[l]));

    // Ring invariant: buf[t % 25] = x[b, t, fp-pair]  (s0 % 25 == 0).
    // Preload 24 history values x[s0-24 .. s0-1] (clamped to 0) into buf[1..24].
    u64 buf[K_DIM];
#pragma unroll
    for (int q = 0; q < K_DIM - 1; ++q) {
        int t = s0 - (K_DIM - 1) + q;
        if (t < 0) t = 0;
        buf[q + 1] = __ldg(&xv[boff + t * P_DIM]);
    }

    for (int j = 0; j < S_TILE; j += K_DIM) {
#pragma unroll
        for (int p = 0; p < K_DIM; ++p) {
            const int t = s0 + j + p;
            const bool in_range = (t < S_DIM);
            u64 cur = 0ULL;                       // bit pattern of {0.f, 0.f}
            if (in_range) cur = __ldg(&xv[boff + t * P_DIM]);
            buf[p] = cur;                         // t % 25 == p

            // out[t] = sum_l w[l] * x[t-24+l] = sum_l pw[l] (*) buf[(p+1+l)%25]
            u64 a0 = 0ULL, a1 = 0ULL, a2 = 0ULL, a3 = 0ULL;
#pragma unroll
            for (int l = 0; l < K_DIM; l += 4) {
                a0 = fma2(pw[l], buf[(p + 1 + l) % K_DIM], a0);
                if (l + 1 < K_DIM) a1 = fma2(pw[l + 1], buf[(p + 2 + l) % K_DIM], a1);
                if (l + 2 < K_DIM) a2 = fma2(pw[l + 2], buf[(p + 3 + l) % K_DIM], a2);
                if (l + 3 < K_DIM) a3 = fma2(pw[l + 3], buf[(p + 4 + l) % K_DIM], a3);
            }
            const u64 acc = add2(add2(a0, a1), add2(a2, a3));

            if (in_range) ov[boff + t * P_DIM] = acc;
        }
    }
}

extern "C" void kernel_launch(void* const* d_in, const int* in_sizes, int n_in,
                              void* d_out, int out_size)
{
    const float* x = (const float*)d_in[0];
    const float* w = (const float*)d_in[1];
    float* out = (float*)d_out;

    const int n_chunks = (S_DIM + S_TILE - 1) / S_TILE;  // 21
    dim3 grid(P_DIM / BLOCK_P, n_chunks, B_DIM);         // (2, 21, 32)
    dim3 block(BLOCK_P);
    adapt_smoothing_kernel<<<grid, block>>>(x, w, out);
}